// round 16
// baseline (speedup 1.0000x reference)
#include <cuda_runtime.h>
#include <math.h>
#define BB 8192
#define TT 100
#define DD 44
#define NCH 4
#define CHB (BB / NCH)
typedef unsigned long long u64;

__device__ __forceinline__ void ffma2(u64& d, u64 a, u64 b) {
    asm("fma.rn.f32x2 %0, %1, %2, %0;" : "+l"(d) : "l"(a), "l"(b));
}
__device__ __forceinline__ float2 up2(u64 v) {
    unsigned lo, hi;
    asm("mov.b64 {%0, %1}, %2;" : "=r"(lo), "=r"(hi) : "l"(v));
    return make_float2(__uint_as_float(lo), __uint_as_float(hi));
}
__device__ __forceinline__ float hadd2(u64 v) { float2 f = up2(v); return f.x + f.y; }
__device__ __forceinline__ u64 d2u(double d) { return (u64)__double_as_longlong(d); }
__device__ __forceinline__ u64 pack2(float lo, float hi) {
    u64 r;
    asm("mov.b64 %0, {%1, %2};" : "=l"(r)
        : "r"(__float_as_uint(lo)), "r"(__float_as_uint(hi)));
    return r;
}
__device__ __forceinline__ float htanh(float x) {
    float r;
    asm("tanh.approx.f32 %0, %1;" : "=f"(r) : "f"(x));
    return r;
}
__device__ __forceinline__ float elu1(float x) { return x > 0.f ? x : (__expf(x) - 1.f); }

__device__ float g_z0[BB * 8];
__device__ float g_kl[BB];
__device__ float g_pz[BB * TT * 8];
__device__ float g_bsum[(BB * TT) / 64];

// ---------------------------------------------------------------------------
// enc (R15 + element offset): 4 independent warps/block, 8 elems each.
__global__ __launch_bounds__(128) void enc_kernel(
    const float* __restrict__ x, const float* __restrict__ mask,
    const float* __restrict__ eps,
    const float* __restrict__ Wi2h, const float* __restrict__ bi2h,
    const float* __restrict__ Wh2o, const float* __restrict__ bh2o, int eg0)
{
    __shared__ __align__(16) float sWp[54 * 128];
    __shared__ __align__(16) float sWoP[32 * 32];
    __shared__ __align__(16) float sxh[32 * 112];

    const int tid = threadIdx.x;
    for (int i = tid; i < 108 * 64; i += 128) {
        const int k = i >> 6, j = i & 63;
        sWp[(k >> 1) * 128 + j * 2 + (k & 1)] = Wi2h[i];
    }
    for (int i = tid; i < 1024; i += 128) {
        const int k = i >> 4, o = i & 15;
        sWoP[(k >> 1) * 32 + o * 2 + (k & 1)] = Wh2o[i];
    }
    for (int i = tid; i < 32 * 112; i += 128) sxh[i] = 0.f;
    __syncthreads();

    const int lane = tid & 31, warp = tid >> 5;
    const int eg = eg0 + blockIdx.x * 32 + warp * 8, eb = warp * 8;
    float* row[8];
#pragma unroll
    for (int e = 0; e < 8; e++) row[e] = &sxh[(eb + e) * 112];

    const u64 biA = pack2(__ldg(&bi2h[2 * lane]), 0.f);
    const u64 biB = pack2(__ldg(&bi2h[2 * lane + 1]), 0.f);

    float rx[11], rm[11];
#pragma unroll
    for (int r = 0; r < 11; r++) {
        const int idx = r * 32 + lane;
        const size_t off = (size_t)(eg + idx / 44) * TT * DD + (size_t)(TT - 1) * DD + idx % 44;
        rx[r] = x[off]; rm[r] = mask[off];
    }

#pragma unroll 1
    for (int t = TT - 1; t >= 0; --t) {
#pragma unroll
        for (int r = 0; r < 11; r++) {
            const int idx = r * 32 + lane;
            sxh[(eb + idx / 44) * 112 + idx % 44] = rx[r] * rm[r];
        }
        __syncwarp();
        if (t > 0) {
#pragma unroll
            for (int r = 0; r < 11; r++) {
                const int idx = r * 32 + lane;
                const size_t off = (size_t)(eg + idx / 44) * TT * DD + (size_t)(t - 1) * DD + idx % 44;
                rx[r] = x[off]; rm[r] = mask[off];
            }
        }
        u64 aA[8], aB[8];
#pragma unroll
        for (int e = 0; e < 8; e++) { aA[e] = biA; aB[e] = biB; }
#pragma unroll 3
        for (int kq = 0; kq < 27; kq++) {
            const double2 wA = *(const double2*)&sWp[(2 * kq) * 128 + 4 * lane];
            const double2 wB = *(const double2*)&sWp[(2 * kq + 1) * 128 + 4 * lane];
            const u64 w0 = d2u(wA.x), w1 = d2u(wA.y), w2 = d2u(wB.x), w3 = d2u(wB.y);
#pragma unroll
            for (int e = 0; e < 8; e++) {
                const double2 vv = *(const double2*)&row[e][4 * kq];
                const u64 v0 = d2u(vv.x), v1 = d2u(vv.y);
                ffma2(aA[e], w0, v0); ffma2(aB[e], w1, v0);
                ffma2(aA[e], w2, v1); ffma2(aB[e], w3, v1);
            }
        }
        __syncwarp();
#pragma unroll
        for (int e = 0; e < 8; e++)
            *(float2*)&row[e][44 + 2 * lane] =
                make_float2(htanh(hadd2(aA[e])), htanh(hadd2(aB[e])));
        __syncwarp();
    }

    const int e = lane >> 2, q = lane & 3;
    const float* re = row[e];
    u64 o0 = pack2(__ldg(&bh2o[4 * q]), 0.f);
    u64 o1 = pack2(__ldg(&bh2o[4 * q + 1]), 0.f);
    u64 o2 = pack2(__ldg(&bh2o[4 * q + 2]), 0.f);
    u64 o3 = pack2(__ldg(&bh2o[4 * q + 3]), 0.f);
#pragma unroll 4
    for (int kp = 0; kp < 32; kp++) {
        const double2 wL = *(const double2*)&sWoP[kp * 32 + 8 * q];
        const double2 wH = *(const double2*)&sWoP[kp * 32 + 8 * q + 4];
        const u64 v = d2u(*(const double*)&re[44 + 2 * kp]);
        ffma2(o0, d2u(wL.x), v); ffma2(o1, d2u(wL.y), v);
        ffma2(o2, d2u(wH.x), v); ffma2(o3, d2u(wH.y), v);
    }
    float s0 = hadd2(o0), s1 = hadd2(o1), s2 = hadd2(o2), s3 = hadd2(o3);
    const float t0 = __shfl_xor_sync(0xffffffffu, s0, 2);
    const float t1 = __shfl_xor_sync(0xffffffffu, s1, 2);
    const float t2 = __shfl_xor_sync(0xffffffffu, s2, 2);
    const float t3 = __shfl_xor_sync(0xffffffffu, s3, 2);
    const int b = eg + e;
    float kl = 0.f;
    if (q < 2) {
        const float4 ep = *(const float4*)&eps[b * 8 + 4 * q];
        float4 z;
        z.x = ep.x * __expf(0.5f * t0) + s0;
        z.y = ep.y * __expf(0.5f * t1) + s1;
        z.z = ep.z * __expf(0.5f * t2) + s2;
        z.w = ep.w * __expf(0.5f * t3) + s3;
        *(float4*)&g_z0[b * 8 + 4 * q] = z;
        kl = -0.5f * t0 + (__expf(t0) + s0 * s0) * 0.5f - 0.5f
           + -0.5f * t1 + (__expf(t1) + s1 * s1) * 0.5f - 0.5f
           + -0.5f * t2 + (__expf(t2) + s2 * s2) * 0.5f - 0.5f
           + -0.5f * t3 + (__expf(t3) + s3 * s3) * 0.5f - 0.5f;
    }
    kl += __shfl_xor_sync(0xffffffffu, kl, 1);
    if (q == 0) g_kl[b] = kl;
}

// ---------------------------------------------------------------------------
// rk4 (R15 + element offset).
__global__ __launch_bounds__(128) void rk4_kernel(
    const float* __restrict__ Wf1, const float* __restrict__ bf1,
    const float* __restrict__ Wf2, const float* __restrict__ bf2,
    const float* __restrict__ Wf3, const float* __restrict__ bf3, int eg0)
{
    __shared__ __align__(16) float sWf1p[4 * 128];
    __shared__ __align__(16) float sWf2p[32 * 128];
    __shared__ __align__(16) float sWf3p[32 * 16];
    __shared__ __align__(16) float sv[32 * 140];

    const int tid = threadIdx.x;
    for (int i = tid; i < 512; i += 128) {
        const int k = i >> 6, j = i & 63;
        sWf1p[(k >> 1) * 128 + j * 2 + (k & 1)] = Wf1[i];
    }
    for (int i = tid; i < 4096; i += 128) {
        const int k = i >> 6, j = i & 63;
        sWf2p[(k >> 1) * 128 + j * 2 + (k & 1)] = Wf2[i];
    }
    for (int i = tid; i < 512; i += 128) {
        const int k = i >> 3, j = i & 7;
        sWf3p[(k >> 1) * 16 + j * 2 + (k & 1)] = Wf3[i];
    }
    __syncthreads();

    const int lane = tid & 31, w = tid >> 5;
    const int eg = eg0 + blockIdx.x * 32 + w * 8, eb = w * 8;
    const int c0 = 2 * lane, c1 = 2 * lane + 1;
    const u64 b1A = pack2(__ldg(&bf1[c0]), 0.f), b1B = pack2(__ldg(&bf1[c1]), 0.f);
    const u64 b2A = pack2(__ldg(&bf2[c0]), 0.f), b2B = pack2(__ldg(&bf2[c1]), 0.f);

    const int eq = lane >> 2, q = lane & 3;
    float* rq = &sv[(eb + eq) * 140];
    const u64 b3A = pack2(__ldg(&bf3[2 * q]), 0.f);
    const u64 b3B = pack2(__ldg(&bf3[2 * q + 1]), 0.f);
    float2 zr = *(const float2*)&g_z0[(eg + eq) * 8 + 2 * q];
    *(float2*)&rq[2 * q] = zr;
    __syncwarp();

    const float dt = 1.f / (float)(TT - 1);

#pragma unroll 1
    for (int t = 0; t < TT; t++) {
        *(float2*)&g_pz[((size_t)(eg + eq) * TT + t) * 8 + 2 * q] = zr;
        if (t == TT - 1) break;
        float2 zac = zr;
#pragma unroll 1
        for (int s = 0; s < 4; s++) {
            const float wco = (s == 0 || s == 3) ? dt / 6.0f : dt / 3.0f;
            const float cco = (s == 2) ? dt : 0.5f * dt;
            u64 aA[8], aB[8];
#pragma unroll
            for (int e = 0; e < 8; e++) { aA[e] = b1A; aB[e] = b1B; }
#pragma unroll
            for (int kq = 0; kq < 2; kq++) {
                const double2 wA = *(const double2*)&sWf1p[(2 * kq) * 128 + 4 * lane];
                const double2 wB = *(const double2*)&sWf1p[(2 * kq + 1) * 128 + 4 * lane];
                const u64 w0 = d2u(wA.x), w1 = d2u(wA.y), w2 = d2u(wB.x), w3 = d2u(wB.y);
#pragma unroll
                for (int e = 0; e < 8; e++) {
                    const double2 vv = *(const double2*)&sv[(eb + e) * 140 + 4 * kq];
                    const u64 v0 = d2u(vv.x), v1 = d2u(vv.y);
                    ffma2(aA[e], w0, v0); ffma2(aB[e], w1, v0);
                    ffma2(aA[e], w2, v1); ffma2(aB[e], w3, v1);
                }
            }
#pragma unroll
            for (int e = 0; e < 8; e++)
                *(float2*)&sv[(eb + e) * 140 + 8 + c0] =
                    make_float2(elu1(hadd2(aA[e])), elu1(hadd2(aB[e])));
            __syncwarp();
#pragma unroll
            for (int e = 0; e < 8; e++) { aA[e] = b2A; aB[e] = b2B; }
#pragma unroll 4
            for (int kq = 0; kq < 16; kq++) {
                const double2 wA = *(const double2*)&sWf2p[(2 * kq) * 128 + 4 * lane];
                const double2 wB = *(const double2*)&sWf2p[(2 * kq + 1) * 128 + 4 * lane];
                const u64 w0 = d2u(wA.x), w1 = d2u(wA.y), w2 = d2u(wB.x), w3 = d2u(wB.y);
#pragma unroll
                for (int e = 0; e < 8; e++) {
                    const double2 vv = *(const double2*)&sv[(eb + e) * 140 + 8 + 4 * kq];
                    const u64 v0 = d2u(vv.x), v1 = d2u(vv.y);
                    ffma2(aA[e], w0, v0); ffma2(aB[e], w1, v0);
                    ffma2(aA[e], w2, v1); ffma2(aB[e], w3, v1);
                }
            }
#pragma unroll
            for (int e = 0; e < 8; e++)
                *(float2*)&sv[(eb + e) * 140 + 72 + c0] =
                    make_float2(elu1(hadd2(aA[e])), elu1(hadd2(aB[e])));
            __syncwarp();
            u64 f0 = b3A, f1 = b3B;
#pragma unroll 4
            for (int i = 0; i < 16; i++) {
                const double2 dA = *(const double2*)&sWf3p[(2 * i) * 16 + 4 * q];
                const double2 dB = *(const double2*)&sWf3p[(2 * i + 1) * 16 + 4 * q];
                const double2 vv = *(const double2*)&rq[72 + 4 * i];
                const u64 v0 = d2u(vv.x), v1 = d2u(vv.y);
                ffma2(f0, d2u(dA.x), v0); ffma2(f1, d2u(dA.y), v0);
                ffma2(f0, d2u(dB.x), v1); ffma2(f1, d2u(dB.y), v1);
            }
            const float fa = hadd2(f0), fb = hadd2(f1);
            zac.x += wco * fa; zac.y += wco * fb;
            float2 zin;
            if (s < 3) { zin.x = zr.x + cco * fa; zin.y = zr.y + cco * fb; }
            else       { zr = zac; zin = zac; }
            *(float2*)&rq[2 * q] = zin;
            __syncwarp();
        }
    }
}

// ---------------------------------------------------------------------------
// dec (R9 + row/bsum offset): fully parallel decoder + SSE, 64 rows/block.
__global__ __launch_bounds__(256) void dec_kernel(
    const float* __restrict__ x, const float* __restrict__ mask,
    const float* __restrict__ Wd1, const float* __restrict__ bd1,
    const float* __restrict__ Wd2, const float* __restrict__ bd2,
    long long row0, int bs0)
{
    __shared__ __align__(16) float sWd1p[4 * 128];
    __shared__ __align__(16) float sWd2p[32 * 128];
    __shared__ __align__(16) float sh[64 * 72];
    __shared__ float sP[8];

    const int tid = threadIdx.x;
    for (int i = tid; i < 512; i += 256) {
        const int k = i >> 6, j = i & 63;
        sWd1p[(k >> 1) * 128 + j * 2 + (k & 1)] = Wd1[i];
    }
    for (int i = tid; i < 4096; i += 256) {
        const int k = i >> 6, j = i & 63;
        sWd2p[(k >> 1) * 128 + j * 2 + (k & 1)] = (j < 44) ? Wd2[k * 44 + j] : 0.f;
    }
    const size_t R0 = (size_t)row0 + (size_t)blockIdx.x * 64;
    for (int i = tid; i < 64 * 4; i += 256) {
        const int rr = i >> 2, jj = (i & 3) * 2;
        *(float2*)&sh[rr * 72 + jj] = *(const float2*)&g_pz[(R0 + rr) * 8 + jj];
    }
    __syncthreads();

    const int lane = tid & 31, warp = tid >> 5;
    const int rb = warp * 8;
    const int c0 = 2 * lane, c1 = 2 * lane + 1;
    const float b1a = __ldg(&bd1[c0]), b1b = __ldg(&bd1[c1]);
    const bool dok = (c0 < 44);
    const float b2a = dok ? __ldg(&bd2[c0]) : 0.f;
    const float b2b = dok ? __ldg(&bd2[c1]) : 0.f;

    u64 aA[8], aB[8];
#pragma unroll
    for (int e = 0; e < 8; e++) { aA[e] = 0ull; aB[e] = 0ull; }
#pragma unroll
    for (int kq = 0; kq < 2; kq++) {
        const double2 wA = *(const double2*)&sWd1p[(2 * kq) * 128 + 4 * lane];
        const double2 wB = *(const double2*)&sWd1p[(2 * kq + 1) * 128 + 4 * lane];
        const u64 w0 = d2u(wA.x), w1 = d2u(wA.y), w2 = d2u(wB.x), w3 = d2u(wB.y);
#pragma unroll
        for (int e = 0; e < 8; e++) {
            const double2 vv = *(const double2*)&sh[(rb + e) * 72 + 4 * kq];
            const u64 v0 = d2u(vv.x), v1 = d2u(vv.y);
            ffma2(aA[e], w0, v0); ffma2(aB[e], w1, v0);
            ffma2(aA[e], w2, v1); ffma2(aB[e], w3, v1);
        }
    }
    __syncwarp();
#pragma unroll
    for (int e = 0; e < 8; e++)
        *(float2*)&sh[(rb + e) * 72 + 8 + c0] =
            make_float2(fmaxf(hadd2(aA[e]) + b1a, 0.f), fmaxf(hadd2(aB[e]) + b1b, 0.f));
    __syncwarp();

#pragma unroll
    for (int e = 0; e < 8; e++) { aA[e] = 0ull; aB[e] = 0ull; }
#pragma unroll 4
    for (int kq = 0; kq < 16; kq++) {
        const double2 wA = *(const double2*)&sWd2p[(2 * kq) * 128 + 4 * lane];
        const double2 wB = *(const double2*)&sWd2p[(2 * kq + 1) * 128 + 4 * lane];
        const u64 w0 = d2u(wA.x), w1 = d2u(wA.y), w2 = d2u(wB.x), w3 = d2u(wB.y);
#pragma unroll
        for (int e = 0; e < 8; e++) {
            const double2 vv = *(const double2*)&sh[(rb + e) * 72 + 8 + 4 * kq];
            const u64 v0 = d2u(vv.x), v1 = d2u(vv.y);
            ffma2(aA[e], w0, v0); ffma2(aB[e], w1, v0);
            ffma2(aA[e], w2, v1); ffma2(aB[e], w3, v1);
        }
    }
    float wtot = 0.f;
    if (dok) {
#pragma unroll
        for (int e = 0; e < 8; e++) {
            const size_t off = (R0 + rb + e) * DD + c0;
            const float2 xv = *(const float2*)&x[off];
            const float2 mv = *(const float2*)&mask[off];
            const float p0 = hadd2(aA[e]) + b2a;
            const float p1 = hadd2(aB[e]) + b2b;
            float da = xv.x - p0, db = xv.y - p1;
            da = (xv.x * mv.x != 0.f) ? 0.f : da;
            db = (xv.y * mv.y != 0.f) ? 0.f : db;
            wtot += da * da + db * db;
        }
    }
    wtot += __shfl_xor_sync(0xffffffffu, wtot, 1);
    wtot += __shfl_xor_sync(0xffffffffu, wtot, 2);
    wtot += __shfl_xor_sync(0xffffffffu, wtot, 4);
    wtot += __shfl_xor_sync(0xffffffffu, wtot, 8);
    wtot += __shfl_xor_sync(0xffffffffu, wtot, 16);
    if (lane == 0) sP[warp] = wtot;
    __syncthreads();
    if (tid == 0) {
        float b = 0.f;
#pragma unroll
        for (int i = 0; i < 8; i++) b += sP[i];
        g_bsum[bs0 + blockIdx.x] = b;
    }
}

// ---------------------------------------------------------------------------
__global__ void reduce_kernel(float* __restrict__ out)
{
    __shared__ float s[1024];
    const int tid = threadIdx.x;
    const float nlv = 2.0f * logf(0.3f);
    const float l2p = logf(6.283185307179586f);
    const float hinv = 0.5f / expf(nlv);
    float ss = 0.f, kk = 0.f;
    for (int i = tid; i < (BB * TT) / 64; i += 1024) ss += g_bsum[i];
    for (int i = tid; i < BB; i += 1024) kk += g_kl[i];
    s[tid] = ss * hinv + kk;
    __syncthreads();
    for (int st = 512; st > 0; st >>= 1) {
        if (tid < st) s[tid] += s[tid + st];
        __syncthreads();
    }
    if (tid == 0)
        out[0] = s[0] / (float)BB + 0.5f * (float)(TT * DD) * (l2p + nlv);
}

// ---------------------------------------------------------------------------
extern "C" void kernel_launch(void* const* d_in, const int* in_sizes, int n_in,
                              void* d_out, int out_size)
{
    const float* x    = (const float*)d_in[0];
    const float* mask = (const float*)d_in[1];
    const float* eps  = (const float*)d_in[2];
    const float* Wi2h = (const float*)d_in[3];
    const float* bi2h = (const float*)d_in[4];
    const float* Wh2o = (const float*)d_in[5];
    const float* bh2o = (const float*)d_in[6];
    const float* Wf1  = (const float*)d_in[7];
    const float* bf1  = (const float*)d_in[8];
    const float* Wf2  = (const float*)d_in[9];
    const float* bf2  = (const float*)d_in[10];
    const float* Wf3  = (const float*)d_in[11];
    const float* bf3  = (const float*)d_in[12];
    const float* Wd1  = (const float*)d_in[13];
    const float* bd1  = (const float*)d_in[14];
    const float* Wd2  = (const float*)d_in[15];
    const float* bd2  = (const float*)d_in[16];

    // One-time stream/event creation (correctness call happens before capture;
    // no device-memory allocation APIs are used here).
    static cudaStream_t sR = 0, sD = 0;
    static cudaEvent_t evE[NCH], evR[NCH], evD;
    static int inited = 0;
    if (!inited) {
        cudaStreamCreateWithFlags(&sR, cudaStreamNonBlocking);
        cudaStreamCreateWithFlags(&sD, cudaStreamNonBlocking);
        for (int c = 0; c < NCH; c++) {
            cudaEventCreateWithFlags(&evE[c], cudaEventDisableTiming);
            cudaEventCreateWithFlags(&evR[c], cudaEventDisableTiming);
        }
        cudaEventCreateWithFlags(&evD, cudaEventDisableTiming);
        inited = 1;
    }

    const int encBlocks = CHB / 32;             // 64
    const int decBlocks = (CHB * TT) / 64;      // 3200

    for (int c = 0; c < NCH; c++) {
        enc_kernel<<<encBlocks, 128>>>(x, mask, eps, Wi2h, bi2h, Wh2o, bh2o,
                                       c * CHB);
        cudaEventRecord(evE[c], 0);

        cudaStreamWaitEvent(sR, evE[c], 0);
        rk4_kernel<<<encBlocks, 128, 0, sR>>>(Wf1, bf1, Wf2, bf2, Wf3, bf3,
                                              c * CHB);
        cudaEventRecord(evR[c], sR);

        cudaStreamWaitEvent(sD, evR[c], 0);
        dec_kernel<<<decBlocks, 256, 0, sD>>>(x, mask, Wd1, bd1, Wd2, bd2,
                                              (long long)c * CHB * TT,
                                              c * decBlocks);
    }
    cudaEventRecord(evD, sD);
    // Join both side streams back into the capture stream.
    cudaStreamWaitEvent(0, evR[NCH - 1], 0);
    cudaStreamWaitEvent(0, evD, 0);

    reduce_kernel<<<1, 1024>>>((float*)d_out);
}

// round 17
// speedup vs baseline: 5.3329x; 5.3329x over previous
#include <cuda_runtime.h>
#include <math.h>
#define BB 8192
#define TT 100
#define DD 44
typedef unsigned long long u64;

__device__ __forceinline__ void ffma2(u64& d, u64 a, u64 b) {
    asm("fma.rn.f32x2 %0, %1, %2, %0;" : "+l"(d) : "l"(a), "l"(b));
}
__device__ __forceinline__ float2 up2(u64 v) {
    unsigned lo, hi;
    asm("mov.b64 {%0, %1}, %2;" : "=r"(lo), "=r"(hi) : "l"(v));
    return make_float2(__uint_as_float(lo), __uint_as_float(hi));
}
__device__ __forceinline__ float hadd2(u64 v) { float2 f = up2(v); return f.x + f.y; }
__device__ __forceinline__ u64 d2u(double d) { return (u64)__double_as_longlong(d); }
__device__ __forceinline__ u64 pack2(float lo, float hi) {
    u64 r;
    asm("mov.b64 %0, {%1, %2};" : "=l"(r)
        : "r"(__float_as_uint(lo)), "r"(__float_as_uint(hi)));
    return r;
}
__device__ __forceinline__ float htanh(float x) {
    float r;
    asm("tanh.approx.f32 %0, %1;" : "=f"(r) : "f"(x));
    return r;
}
__device__ __forceinline__ float elu1(float x) { return x > 0.f ? x : (__expf(x) - 1.f); }

__device__ float g_z0[BB * 8];
__device__ float g_kl[BB];
__device__ float g_pz[BB * TT * 8];
__device__ float g_bsum[(BB * TT) / 64];
__device__ float g_part[64];

// ---------------------------------------------------------------------------
// enc (R15 verbatim): 4 independent warps/block, 8 elems each.
__global__ __launch_bounds__(128) void enc_kernel(
    const float* __restrict__ x, const float* __restrict__ mask,
    const float* __restrict__ eps,
    const float* __restrict__ Wi2h, const float* __restrict__ bi2h,
    const float* __restrict__ Wh2o, const float* __restrict__ bh2o)
{
    __shared__ __align__(16) float sWp[54 * 128];
    __shared__ __align__(16) float sWoP[32 * 32];
    __shared__ __align__(16) float sxh[32 * 112];

    const int tid = threadIdx.x;
    for (int i = tid; i < 108 * 64; i += 128) {
        const int k = i >> 6, j = i & 63;
        sWp[(k >> 1) * 128 + j * 2 + (k & 1)] = Wi2h[i];
    }
    for (int i = tid; i < 1024; i += 128) {
        const int k = i >> 4, o = i & 15;
        sWoP[(k >> 1) * 32 + o * 2 + (k & 1)] = Wh2o[i];
    }
    for (int i = tid; i < 32 * 112; i += 128) sxh[i] = 0.f;
    __syncthreads();

    const int lane = tid & 31, warp = tid >> 5;
    const int eg = blockIdx.x * 32 + warp * 8, eb = warp * 8;
    float* row[8];
#pragma unroll
    for (int e = 0; e < 8; e++) row[e] = &sxh[(eb + e) * 112];

    const u64 biA = pack2(__ldg(&bi2h[2 * lane]), 0.f);
    const u64 biB = pack2(__ldg(&bi2h[2 * lane + 1]), 0.f);

    float rx[11], rm[11];
#pragma unroll
    for (int r = 0; r < 11; r++) {
        const int idx = r * 32 + lane;
        const size_t off = (size_t)(eg + idx / 44) * TT * DD + (size_t)(TT - 1) * DD + idx % 44;
        rx[r] = x[off]; rm[r] = mask[off];
    }

#pragma unroll 1
    for (int t = TT - 1; t >= 0; --t) {
#pragma unroll
        for (int r = 0; r < 11; r++) {
            const int idx = r * 32 + lane;
            sxh[(eb + idx / 44) * 112 + idx % 44] = rx[r] * rm[r];
        }
        __syncwarp();
        if (t > 0) {
#pragma unroll
            for (int r = 0; r < 11; r++) {
                const int idx = r * 32 + lane;
                const size_t off = (size_t)(eg + idx / 44) * TT * DD + (size_t)(t - 1) * DD + idx % 44;
                rx[r] = x[off]; rm[r] = mask[off];
            }
        }
        u64 aA[8], aB[8];
#pragma unroll
        for (int e = 0; e < 8; e++) { aA[e] = biA; aB[e] = biB; }
#pragma unroll 3
        for (int kq = 0; kq < 27; kq++) {
            const double2 wA = *(const double2*)&sWp[(2 * kq) * 128 + 4 * lane];
            const double2 wB = *(const double2*)&sWp[(2 * kq + 1) * 128 + 4 * lane];
            const u64 w0 = d2u(wA.x), w1 = d2u(wA.y), w2 = d2u(wB.x), w3 = d2u(wB.y);
#pragma unroll
            for (int e = 0; e < 8; e++) {
                const double2 vv = *(const double2*)&row[e][4 * kq];
                const u64 v0 = d2u(vv.x), v1 = d2u(vv.y);
                ffma2(aA[e], w0, v0); ffma2(aB[e], w1, v0);
                ffma2(aA[e], w2, v1); ffma2(aB[e], w3, v1);
            }
        }
        __syncwarp();
#pragma unroll
        for (int e = 0; e < 8; e++)
            *(float2*)&row[e][44 + 2 * lane] =
                make_float2(htanh(hadd2(aA[e])), htanh(hadd2(aB[e])));
        __syncwarp();
    }

    const int e = lane >> 2, q = lane & 3;
    const float* re = row[e];
    u64 o0 = pack2(__ldg(&bh2o[4 * q]), 0.f);
    u64 o1 = pack2(__ldg(&bh2o[4 * q + 1]), 0.f);
    u64 o2 = pack2(__ldg(&bh2o[4 * q + 2]), 0.f);
    u64 o3 = pack2(__ldg(&bh2o[4 * q + 3]), 0.f);
#pragma unroll 4
    for (int kp = 0; kp < 32; kp++) {
        const double2 wL = *(const double2*)&sWoP[kp * 32 + 8 * q];
        const double2 wH = *(const double2*)&sWoP[kp * 32 + 8 * q + 4];
        const u64 v = d2u(*(const double*)&re[44 + 2 * kp]);
        ffma2(o0, d2u(wL.x), v); ffma2(o1, d2u(wL.y), v);
        ffma2(o2, d2u(wH.x), v); ffma2(o3, d2u(wH.y), v);
    }
    float s0 = hadd2(o0), s1 = hadd2(o1), s2 = hadd2(o2), s3 = hadd2(o3);
    const float t0 = __shfl_xor_sync(0xffffffffu, s0, 2);
    const float t1 = __shfl_xor_sync(0xffffffffu, s1, 2);
    const float t2 = __shfl_xor_sync(0xffffffffu, s2, 2);
    const float t3 = __shfl_xor_sync(0xffffffffu, s3, 2);
    const int b = eg + e;
    float kl = 0.f;
    if (q < 2) {
        const float4 ep = *(const float4*)&eps[b * 8 + 4 * q];
        float4 z;
        z.x = ep.x * __expf(0.5f * t0) + s0;
        z.y = ep.y * __expf(0.5f * t1) + s1;
        z.z = ep.z * __expf(0.5f * t2) + s2;
        z.w = ep.w * __expf(0.5f * t3) + s3;
        *(float4*)&g_z0[b * 8 + 4 * q] = z;
        kl = -0.5f * t0 + (__expf(t0) + s0 * s0) * 0.5f - 0.5f
           + -0.5f * t1 + (__expf(t1) + s1 * s1) * 0.5f - 0.5f
           + -0.5f * t2 + (__expf(t2) + s2 * s2) * 0.5f - 0.5f
           + -0.5f * t3 + (__expf(t3) + s3 * s3) * 0.5f - 0.5f;
    }
    kl += __shfl_xor_sync(0xffffffffu, kl, 1);
    if (q == 0) g_kl[b] = kl;
}

// ---------------------------------------------------------------------------
// rk4 (R15 + hoisted final pz store).
__global__ __launch_bounds__(128) void rk4_kernel(
    const float* __restrict__ Wf1, const float* __restrict__ bf1,
    const float* __restrict__ Wf2, const float* __restrict__ bf2,
    const float* __restrict__ Wf3, const float* __restrict__ bf3)
{
    __shared__ __align__(16) float sWf1p[4 * 128];
    __shared__ __align__(16) float sWf2p[32 * 128];
    __shared__ __align__(16) float sWf3p[32 * 16];
    __shared__ __align__(16) float sv[32 * 140];

    const int tid = threadIdx.x;
    for (int i = tid; i < 512; i += 128) {
        const int k = i >> 6, j = i & 63;
        sWf1p[(k >> 1) * 128 + j * 2 + (k & 1)] = Wf1[i];
    }
    for (int i = tid; i < 4096; i += 128) {
        const int k = i >> 6, j = i & 63;
        sWf2p[(k >> 1) * 128 + j * 2 + (k & 1)] = Wf2[i];
    }
    for (int i = tid; i < 512; i += 128) {
        const int k = i >> 3, j = i & 7;
        sWf3p[(k >> 1) * 16 + j * 2 + (k & 1)] = Wf3[i];
    }
    __syncthreads();

    const int lane = tid & 31, w = tid >> 5;
    const int eg = blockIdx.x * 32 + w * 8, eb = w * 8;
    const int c0 = 2 * lane, c1 = 2 * lane + 1;
    const u64 b1A = pack2(__ldg(&bf1[c0]), 0.f), b1B = pack2(__ldg(&bf1[c1]), 0.f);
    const u64 b2A = pack2(__ldg(&bf2[c0]), 0.f), b2B = pack2(__ldg(&bf2[c1]), 0.f);

    const int eq = lane >> 2, q = lane & 3;
    float* rq = &sv[(eb + eq) * 140];
    const u64 b3A = pack2(__ldg(&bf3[2 * q]), 0.f);
    const u64 b3B = pack2(__ldg(&bf3[2 * q + 1]), 0.f);
    float2 zr = *(const float2*)&g_z0[(eg + eq) * 8 + 2 * q];
    *(float2*)&rq[2 * q] = zr;
    __syncwarp();

    const float dt = 1.f / (float)(TT - 1);
    float* pzb = &g_pz[((size_t)(eg + eq) * TT) * 8 + 2 * q];

#pragma unroll 1
    for (int t = 0; t < TT - 1; t++) {
        *(float2*)&pzb[(size_t)t * 8] = zr;
        float2 zac = zr;
#pragma unroll 1
        for (int s = 0; s < 4; s++) {
            const float wco = (s == 0 || s == 3) ? dt / 6.0f : dt / 3.0f;
            const float cco = (s == 2) ? dt : 0.5f * dt;
            // ---- GEMV1: h1 = elu(z @ Wf1 + b1), K=8 ----
            u64 aA[8], aB[8];
#pragma unroll
            for (int e = 0; e < 8; e++) { aA[e] = b1A; aB[e] = b1B; }
#pragma unroll
            for (int kq = 0; kq < 2; kq++) {
                const double2 wA = *(const double2*)&sWf1p[(2 * kq) * 128 + 4 * lane];
                const double2 wB = *(const double2*)&sWf1p[(2 * kq + 1) * 128 + 4 * lane];
                const u64 w0 = d2u(wA.x), w1 = d2u(wA.y), w2 = d2u(wB.x), w3 = d2u(wB.y);
#pragma unroll
                for (int e = 0; e < 8; e++) {
                    const double2 vv = *(const double2*)&sv[(eb + e) * 140 + 4 * kq];
                    const u64 v0 = d2u(vv.x), v1 = d2u(vv.y);
                    ffma2(aA[e], w0, v0); ffma2(aB[e], w1, v0);
                    ffma2(aA[e], w2, v1); ffma2(aB[e], w3, v1);
                }
            }
#pragma unroll
            for (int e = 0; e < 8; e++)
                *(float2*)&sv[(eb + e) * 140 + 8 + c0] =
                    make_float2(elu1(hadd2(aA[e])), elu1(hadd2(aB[e])));
            __syncwarp();
            // ---- GEMV2: h2 = elu(h1 @ Wf2 + b2), K=64, unroll 4 ----
#pragma unroll
            for (int e = 0; e < 8; e++) { aA[e] = b2A; aB[e] = b2B; }
#pragma unroll 4
            for (int kq = 0; kq < 16; kq++) {
                const double2 wA = *(const double2*)&sWf2p[(2 * kq) * 128 + 4 * lane];
                const double2 wB = *(const double2*)&sWf2p[(2 * kq + 1) * 128 + 4 * lane];
                const u64 w0 = d2u(wA.x), w1 = d2u(wA.y), w2 = d2u(wB.x), w3 = d2u(wB.y);
#pragma unroll
                for (int e = 0; e < 8; e++) {
                    const double2 vv = *(const double2*)&sv[(eb + e) * 140 + 8 + 4 * kq];
                    const u64 v0 = d2u(vv.x), v1 = d2u(vv.y);
                    ffma2(aA[e], w0, v0); ffma2(aB[e], w1, v0);
                    ffma2(aA[e], w2, v1); ffma2(aB[e], w3, v1);
                }
            }
#pragma unroll
            for (int e = 0; e < 8; e++)
                *(float2*)&sv[(eb + e) * 140 + 72 + c0] =
                    make_float2(elu1(hadd2(aA[e])), elu1(hadd2(aB[e])));
            __syncwarp();
            // ---- GEMV3: f = h2 @ Wf3 + b3 (elem eq, cols 2q,2q+1) ----
            u64 f0 = b3A, f1 = b3B;
#pragma unroll 4
            for (int i = 0; i < 16; i++) {
                const double2 dA = *(const double2*)&sWf3p[(2 * i) * 16 + 4 * q];
                const double2 dB = *(const double2*)&sWf3p[(2 * i + 1) * 16 + 4 * q];
                const double2 vv = *(const double2*)&rq[72 + 4 * i];
                const u64 v0 = d2u(vv.x), v1 = d2u(vv.y);
                ffma2(f0, d2u(dA.x), v0); ffma2(f1, d2u(dA.y), v0);
                ffma2(f0, d2u(dB.x), v1); ffma2(f1, d2u(dB.y), v1);
            }
            const float fa = hadd2(f0), fb = hadd2(f1);
            zac.x += wco * fa; zac.y += wco * fb;
            float2 zin;
            if (s < 3) { zin.x = zr.x + cco * fa; zin.y = zr.y + cco * fb; }
            else       { zr = zac; zin = zac; }
            *(float2*)&rq[2 * q] = zin;
            __syncwarp();
        }
    }
    *(float2*)&pzb[(size_t)(TT - 1) * 8] = zr;
}

// ---------------------------------------------------------------------------
// dec (R9 verbatim): fully parallel decoder + SSE, 64 rows/block.
__global__ __launch_bounds__(256) void dec_kernel(
    const float* __restrict__ x, const float* __restrict__ mask,
    const float* __restrict__ Wd1, const float* __restrict__ bd1,
    const float* __restrict__ Wd2, const float* __restrict__ bd2)
{
    __shared__ __align__(16) float sWd1p[4 * 128];
    __shared__ __align__(16) float sWd2p[32 * 128];
    __shared__ __align__(16) float sh[64 * 72];
    __shared__ float sP[8];

    const int tid = threadIdx.x;
    for (int i = tid; i < 512; i += 256) {
        const int k = i >> 6, j = i & 63;
        sWd1p[(k >> 1) * 128 + j * 2 + (k & 1)] = Wd1[i];
    }
    for (int i = tid; i < 4096; i += 256) {
        const int k = i >> 6, j = i & 63;
        sWd2p[(k >> 1) * 128 + j * 2 + (k & 1)] = (j < 44) ? Wd2[k * 44 + j] : 0.f;
    }
    const size_t R0 = (size_t)blockIdx.x * 64;
    for (int i = tid; i < 64 * 4; i += 256) {
        const int rr = i >> 2, jj = (i & 3) * 2;
        *(float2*)&sh[rr * 72 + jj] = *(const float2*)&g_pz[(R0 + rr) * 8 + jj];
    }
    __syncthreads();

    const int lane = tid & 31, warp = tid >> 5;
    const int rb = warp * 8;
    const int c0 = 2 * lane, c1 = 2 * lane + 1;
    const float b1a = __ldg(&bd1[c0]), b1b = __ldg(&bd1[c1]);
    const bool dok = (c0 < 44);
    const float b2a = dok ? __ldg(&bd2[c0]) : 0.f;
    const float b2b = dok ? __ldg(&bd2[c1]) : 0.f;

    u64 aA[8], aB[8];
#pragma unroll
    for (int e = 0; e < 8; e++) { aA[e] = 0ull; aB[e] = 0ull; }
#pragma unroll
    for (int kq = 0; kq < 2; kq++) {
        const double2 wA = *(const double2*)&sWd1p[(2 * kq) * 128 + 4 * lane];
        const double2 wB = *(const double2*)&sWd1p[(2 * kq + 1) * 128 + 4 * lane];
        const u64 w0 = d2u(wA.x), w1 = d2u(wA.y), w2 = d2u(wB.x), w3 = d2u(wB.y);
#pragma unroll
        for (int e = 0; e < 8; e++) {
            const double2 vv = *(const double2*)&sh[(rb + e) * 72 + 4 * kq];
            const u64 v0 = d2u(vv.x), v1 = d2u(vv.y);
            ffma2(aA[e], w0, v0); ffma2(aB[e], w1, v0);
            ffma2(aA[e], w2, v1); ffma2(aB[e], w3, v1);
        }
    }
    __syncwarp();
#pragma unroll
    for (int e = 0; e < 8; e++)
        *(float2*)&sh[(rb + e) * 72 + 8 + c0] =
            make_float2(fmaxf(hadd2(aA[e]) + b1a, 0.f), fmaxf(hadd2(aB[e]) + b1b, 0.f));
    __syncwarp();

#pragma unroll
    for (int e = 0; e < 8; e++) { aA[e] = 0ull; aB[e] = 0ull; }
#pragma unroll 4
    for (int kq = 0; kq < 16; kq++) {
        const double2 wA = *(const double2*)&sWd2p[(2 * kq) * 128 + 4 * lane];
        const double2 wB = *(const double2*)&sWd2p[(2 * kq + 1) * 128 + 4 * lane];
        const u64 w0 = d2u(wA.x), w1 = d2u(wA.y), w2 = d2u(wB.x), w3 = d2u(wB.y);
#pragma unroll
        for (int e = 0; e < 8; e++) {
            const double2 vv = *(const double2*)&sh[(rb + e) * 72 + 8 + 4 * kq];
            const u64 v0 = d2u(vv.x), v1 = d2u(vv.y);
            ffma2(aA[e], w0, v0); ffma2(aB[e], w1, v0);
            ffma2(aA[e], w2, v1); ffma2(aB[e], w3, v1);
        }
    }
    float wtot = 0.f;
    if (dok) {
#pragma unroll
        for (int e = 0; e < 8; e++) {
            const size_t off = (R0 + rb + e) * DD + c0;
            const float2 xv = *(const float2*)&x[off];
            const float2 mv = *(const float2*)&mask[off];
            const float p0 = hadd2(aA[e]) + b2a;
            const float p1 = hadd2(aB[e]) + b2b;
            float da = xv.x - p0, db = xv.y - p1;
            da = (xv.x * mv.x != 0.f) ? 0.f : da;
            db = (xv.y * mv.y != 0.f) ? 0.f : db;
            wtot += da * da + db * db;
        }
    }
    wtot += __shfl_xor_sync(0xffffffffu, wtot, 1);
    wtot += __shfl_xor_sync(0xffffffffu, wtot, 2);
    wtot += __shfl_xor_sync(0xffffffffu, wtot, 4);
    wtot += __shfl_xor_sync(0xffffffffu, wtot, 8);
    wtot += __shfl_xor_sync(0xffffffffu, wtot, 16);
    if (lane == 0) sP[warp] = wtot;
    __syncthreads();
    if (tid == 0) {
        float b = 0.f;
#pragma unroll
        for (int i = 0; i < 8; i++) b += sP[i];
        g_bsum[blockIdx.x] = b;
    }
}

// ---------------------------------------------------------------------------
// reduce stage 1: 64 blocks x 256 threads -> g_part[64]
__global__ void reduce1_kernel()
{
    __shared__ float s[256];
    const int tid = threadIdx.x;
    const float nlv = 2.0f * logf(0.3f);
    const float hinv = 0.5f / expf(nlv);
    float ss = 0.f, kk = 0.f;
    const int NB = (BB * TT) / 64;   // 12800
    for (int i = blockIdx.x * 256 + tid; i < NB; i += 64 * 256) ss += g_bsum[i];
    for (int i = blockIdx.x * 256 + tid; i < BB; i += 64 * 256) kk += g_kl[i];
    s[tid] = ss * hinv + kk;
    __syncthreads();
    for (int st = 128; st > 0; st >>= 1) {
        if (tid < st) s[tid] += s[tid + st];
        __syncthreads();
    }
    if (tid == 0) g_part[blockIdx.x] = s[0];
}

// reduce stage 2: one warp folds 64 partials
__global__ void reduce2_kernel(float* __restrict__ out)
{
    const int tid = threadIdx.x;
    float v = g_part[tid] + g_part[tid + 32];
    v += __shfl_xor_sync(0xffffffffu, v, 16);
    v += __shfl_xor_sync(0xffffffffu, v, 8);
    v += __shfl_xor_sync(0xffffffffu, v, 4);
    v += __shfl_xor_sync(0xffffffffu, v, 2);
    v += __shfl_xor_sync(0xffffffffu, v, 1);
    if (tid == 0) {
        const float nlv = 2.0f * logf(0.3f);
        const float l2p = logf(6.283185307179586f);
        out[0] = v / (float)BB + 0.5f * (float)(TT * DD) * (l2p + nlv);
    }
}

// ---------------------------------------------------------------------------
extern "C" void kernel_launch(void* const* d_in, const int* in_sizes, int n_in,
                              void* d_out, int out_size)
{
    const float* x    = (const float*)d_in[0];
    const float* mask = (const float*)d_in[1];
    const float* eps  = (const float*)d_in[2];
    const float* Wi2h = (const float*)d_in[3];
    const float* bi2h = (const float*)d_in[4];
    const float* Wh2o = (const float*)d_in[5];
    const float* bh2o = (const float*)d_in[6];
    const float* Wf1  = (const float*)d_in[7];
    const float* bf1  = (const float*)d_in[8];
    const float* Wf2  = (const float*)d_in[9];
    const float* bf2  = (const float*)d_in[10];
    const float* Wf3  = (const float*)d_in[11];
    const float* bf3  = (const float*)d_in[12];
    const float* Wd1  = (const float*)d_in[13];
    const float* bd1  = (const float*)d_in[14];
    const float* Wd2  = (const float*)d_in[15];
    const float* bd2  = (const float*)d_in[16];

    enc_kernel<<<BB / 32, 128>>>(x, mask, eps, Wi2h, bi2h, Wh2o, bh2o);
    rk4_kernel<<<BB / 32, 128>>>(Wf1, bf1, Wf2, bf2, Wf3, bf3);
    dec_kernel<<<(BB * TT) / 64, 256>>>(x, mask, Wd1, bd1, Wd2, bd2);
    reduce1_kernel<<<64, 256>>>();
    reduce2_kernel<<<1, 32>>>((float*)d_out);
}